// round 1
// baseline (speedup 1.0000x reference)
#include <cuda_runtime.h>
#include <cstdint>

// Problem constants (fixed by the dataset: source/target are [4096, 256] f32)
#define B_ROWS 4096
#define NROWS  8192
#define D      256

#define BM 128
#define BN 128
#define BK 16
#define LDA 132   // padded smem row stride (multiple of 4 for float4 alignment)

// ---- device scratch (no allocations allowed) ----
__device__ float  g_sq[NROWS];
__device__ double g_colsum[D];
__device__ double g_sumsq;
__device__ double g_acc;
__device__ float  g_c2;   // exp2 scale: u = exp2(c2 * L2) = exp(-L2/(16*bw))

__device__ __forceinline__ float ex2f(float x) {
    float y;
    asm("ex2.approx.ftz.f32 %0, %1;" : "=f"(y) : "f"(x));
    return y;
}

// ---------------------------------------------------------------------------
// k_init: zero the accumulators (runs every graph replay, keeps launch
// deterministic).
// ---------------------------------------------------------------------------
__global__ void k_init() {
    int t = threadIdx.x;
    if (t < D) g_colsum[t] = 0.0;
    if (t == 0) { g_sumsq = 0.0; g_acc = 0.0; }
}

// ---------------------------------------------------------------------------
// k_rows: per-row squared norms g_sq[i], plus global sum of squares and
// per-column sums (for the analytic bandwidth).
// grid = 256 blocks x 256 threads; block b handles rows [b*32, b*32+32).
// ---------------------------------------------------------------------------
__global__ void k_rows(const float* __restrict__ src, const float* __restrict__ tgt) {
    __shared__ float red[256];
    int t  = threadIdx.x;
    int r0 = blockIdx.x * 32;

    double colpart = 0.0;
    double sumsq_part = 0.0;

    for (int r = 0; r < 32; r++) {
        int row = r0 + r;
        const float* p = (row < B_ROWS) ? (src + (size_t)row * D)
                                        : (tgt + (size_t)(row - B_ROWS) * D);
        float v = p[t];
        colpart += (double)v;

        red[t] = v * v;
        __syncthreads();
        #pragma unroll
        for (int s = 128; s > 0; s >>= 1) {
            if (t < s) red[t] += red[t + s];
            __syncthreads();
        }
        if (t == 0) {
            g_sq[row] = red[0];
            sumsq_part += (double)red[0];
        }
        __syncthreads();
    }
    atomicAdd(&g_colsum[t], colpart);
    if (t == 0) atomicAdd(&g_sumsq, sumsq_part);
}

// ---------------------------------------------------------------------------
// k_bw: bandwidth = sum(L2)/(n^2-n)/4, with
//   sum(L2) = 2n*sumsq - 2*|colsum|^2   (no n^2 matrix needed).
// Stores c2 = -1/(16*bw*ln2) so u = exp2(c2*L2) = exp(-L2/(16*bw)).
// ---------------------------------------------------------------------------
__global__ void k_bw() {
    __shared__ double red[256];
    int t = threadIdx.x;
    double c = g_colsum[t];
    red[t] = c * c;
    __syncthreads();
    #pragma unroll
    for (int s = 128; s > 0; s >>= 1) {
        if (t < s) red[t] += red[t + s];
        __syncthreads();
    }
    if (t == 0) {
        double n = (double)NROWS;
        double sumL2 = 2.0 * n * g_sumsq - 2.0 * red[0];
        double bw = sumL2 / (n * n - n);
        bw *= 0.25;  // / KERNEL_MUL^(KERNEL_NUM//2) = / 2^2
        g_c2 = (float)(-1.0 / (16.0 * bw * 0.6931471805599453094));
    }
}

// ---------------------------------------------------------------------------
// k_main: upper-triangular tiled GEMM G = T T^t fused with the MMD epilogue.
//   result contribution: sum_{i<j} w_i w_j (u + u^2 + u^4 + u^8 + u^16),
//   u = exp2(c2 * L2_ij), L2 = sq_i + sq_j - 2 G_ij.
// 128x128 tile per block, 256 threads, 8x8 microtile per thread, BK=16.
// Tiles never straddle the source/target boundary (4096 % 128 == 0).
// ---------------------------------------------------------------------------
__global__ void __launch_bounds__(256, 2)
k_main(const float* __restrict__ src, const float* __restrict__ tgt) {
    int J = blockIdx.x;  // column tile
    int I = blockIdx.y;  // row tile
    if (J < I) return;   // upper triangle only

    __shared__ float As[BK][LDA];
    __shared__ float Bs[BK][LDA];
    __shared__ double sred[256];

    const int TILES_SRC = B_ROWS / BM;  // 32
    const float* Abase = (I < TILES_SRC) ? (src + (size_t)I * BM * D)
                                         : (tgt + (size_t)(I - TILES_SRC) * BM * D);
    const float* Bbase = (J < TILES_SRC) ? (src + (size_t)J * BM * D)
                                         : (tgt + (size_t)(J - TILES_SRC) * BM * D);
    const double sign = ((I < TILES_SRC) == (J < TILES_SRC)) ? 1.0 : -1.0;

    int t  = threadIdx.x;
    int lr = t >> 2;          // 0..63 : loader row (also +64)
    int lc = (t & 3) * 4;     // 0,4,8,12 : loader col within BK

    float acc[8][8];
    #pragma unroll
    for (int i = 0; i < 8; i++)
        #pragma unroll
        for (int j = 0; j < 8; j++) acc[i][j] = 0.f;

    const int tm = (t >> 4) * 8;   // 0..120
    const int tn = (t & 15) * 8;   // 0..120

    for (int kt = 0; kt < D / BK; kt++) {
        // load 128x16 of A and B, stored K-major (transposed) in smem
        #pragma unroll
        for (int h = 0; h < 2; h++) {
            int row = lr + h * 64;
            float4 va = *(const float4*)(Abase + (size_t)row * D + kt * BK + lc);
            As[lc + 0][row] = va.x; As[lc + 1][row] = va.y;
            As[lc + 2][row] = va.z; As[lc + 3][row] = va.w;
            float4 vb = *(const float4*)(Bbase + (size_t)row * D + kt * BK + lc);
            Bs[lc + 0][row] = vb.x; Bs[lc + 1][row] = vb.y;
            Bs[lc + 2][row] = vb.z; Bs[lc + 3][row] = vb.w;
        }
        __syncthreads();

        #pragma unroll
        for (int k = 0; k < BK; k++) {
            float af[8], bf[8];
            *(float4*)(af)     = *(const float4*)&As[k][tm];
            *(float4*)(af + 4) = *(const float4*)&As[k][tm + 4];
            *(float4*)(bf)     = *(const float4*)&Bs[k][tn];
            *(float4*)(bf + 4) = *(const float4*)&Bs[k][tn + 4];
            #pragma unroll
            for (int mi = 0; mi < 8; mi++)
                #pragma unroll
                for (int ni = 0; ni < 8; ni++)
                    acc[mi][ni] += af[mi] * bf[ni];
        }
        __syncthreads();
    }

    // fused epilogue: L2 -> u -> K = u + u^2 + u^4 + u^8 + u^16, masked i<j
    const float c2 = g_c2;
    float sqi[8], sqj[8];
    #pragma unroll
    for (int mi = 0; mi < 8; mi++) sqi[mi] = g_sq[I * BM + tm + mi];
    #pragma unroll
    for (int ni = 0; ni < 8; ni++) sqj[ni] = g_sq[J * BN + tn + ni];

    float facc = 0.f;
    const bool diag = (I == J);
    #pragma unroll
    for (int mi = 0; mi < 8; mi++) {
        #pragma unroll
        for (int ni = 0; ni < 8; ni++) {
            float l2 = sqi[mi] + sqj[ni] - 2.f * acc[mi][ni];
            float u  = ex2f(c2 * l2);
            float u2 = u * u, u4 = u2 * u2, u8 = u4 * u4, u16 = u8 * u8;
            float kv = ((u + u2) + (u4 + u8)) + u16;
            bool take = !diag || ((tn + ni) > (tm + mi));  // strict upper in diag tile
            facc += take ? kv : 0.f;
        }
    }

    // block reduction in double, one atomic per block
    sred[t] = (double)facc * sign;
    __syncthreads();
    #pragma unroll
    for (int s = 128; s > 0; s >>= 1) {
        if (t < s) sred[t] += sred[t + s];
        __syncthreads();
    }
    if (t == 0) atomicAdd(&g_acc, sred[0]);
}

// ---------------------------------------------------------------------------
// k_fin: result = (2*sum_{i<j} + 5*n) / b^2   (diagonal K_ii = 5 exactly)
// ---------------------------------------------------------------------------
__global__ void k_fin(float* out) {
    out[0] = (float)((2.0 * g_acc + 5.0 * (double)NROWS)
                     / ((double)B_ROWS * (double)B_ROWS));
}

extern "C" void kernel_launch(void* const* d_in, const int* in_sizes, int n_in,
                              void* d_out, int out_size) {
    const float* src = (const float*)d_in[0];
    const float* tgt = (const float*)d_in[1];
    float* out = (float*)d_out;

    k_init<<<1, 256>>>();
    k_rows<<<NROWS / 32, 256>>>(src, tgt);
    k_bw<<<1, 256>>>();
    dim3 grid(NROWS / BN, NROWS / BM);
    k_main<<<grid, 256>>>(src, tgt);
    k_fin<<<1, 1>>>(out);
}

// round 3
// speedup vs baseline: 4.4421x; 4.4421x over previous
#include <cuda_runtime.h>
#include <cuda_bf16.h>
#include <cstdint>

// Problem constants (fixed: source/target are [4096, 256] f32)
#define B_ROWS 4096
#define NROWS  8192
#define D      256
#define TILE   128
#define NT     (NROWS / TILE)          // 64 tiles per side
#define NPAIRS (NT * (NT + 1) / 2)     // 2080 upper-tri tile pairs
#define BK     64                      // K chunk
#define NKC    (D / BK)                // 4 chunks
#define ABYTES (TILE * BK * 2)         // 16384 bytes per operand chunk
#define BUFB   (2 * ABYTES)            // 32768 bytes per double-buffer slot

// ---- device scratch (no allocations allowed) ----
__device__ __align__(16) __nv_bfloat16 g_bf16[NROWS * D];  // 4 MB converted inputs
__device__ float  g_sq[NROWS];
__device__ double g_colsum[D];
__device__ double g_sumsq;
__device__ double g_acc;
__device__ float  g_c2;   // u = exp2(c2 * L2) = exp(-L2/(16*bw))

// ---------------------------------------------------------------------------
// PTX helpers (baseline PTX only -- compiles for compute_103)
// ---------------------------------------------------------------------------
__device__ __forceinline__ float ex2f(float x) {
    float y; asm("ex2.approx.ftz.f32 %0, %1;" : "=f"(y) : "f"(x)); return y;
}
__device__ __forceinline__ uint32_t smem_u32(const void* p) {
    uint32_t a;
    asm("{ .reg .u64 t; cvta.to.shared.u64 t, %1; cvt.u32.u64 %0, t; }"
        : "=r"(a) : "l"(p));
    return a;
}
__device__ __forceinline__ void cpasync16(uint32_t dst, const void* src) {
    asm volatile("cp.async.cg.shared.global [%0], [%1], 16;"
                 :: "r"(dst), "l"(src) : "memory");
}
#define CP_COMMIT() asm volatile("cp.async.commit_group;" ::: "memory")
#define CP_WAIT(n)  asm volatile("cp.async.wait_group %0;" :: "n"(n) : "memory")

#define LDSM4(r, addr) \
    asm volatile("ldmatrix.sync.aligned.m8n8.x4.shared.b16 {%0,%1,%2,%3}, [%4];" \
                 : "=r"((r)[0]), "=r"((r)[1]), "=r"((r)[2]), "=r"((r)[3]) \
                 : "r"(addr))

#define MMA16816(d, a, b0, b1) \
    asm volatile("mma.sync.aligned.m16n8k16.row.col.f32.bf16.bf16.f32 " \
                 "{%0,%1,%2,%3}, {%4,%5,%6,%7}, {%8,%9}, {%0,%1,%2,%3};" \
                 : "+f"((d)[0]), "+f"((d)[1]), "+f"((d)[2]), "+f"((d)[3]) \
                 : "r"((a)[0]), "r"((a)[1]), "r"((a)[2]), "r"((a)[3]), \
                   "r"(b0), "r"(b1))

// ---------------------------------------------------------------------------
// k_init: zero accumulators each replay
// ---------------------------------------------------------------------------
__global__ void k_init() {
    int t = threadIdx.x;
    if (t < D) g_colsum[t] = 0.0;
    if (t == 0) { g_sumsq = 0.0; g_acc = 0.0; }
}

// ---------------------------------------------------------------------------
// k_prep: f32 -> bf16 conversion + row sq-norms + column sums + sum of squares
// block = 256 threads = 8 warps, one row per warp. grid = 1024.
// ---------------------------------------------------------------------------
__global__ void k_prep(const float* __restrict__ src, const float* __restrict__ tgt) {
    __shared__ double scol[D];
    __shared__ float  swsq[8];
    int t = threadIdx.x, w = t >> 5, l = t & 31;
    scol[t] = 0.0;
    __syncthreads();

    int row = blockIdx.x * 8 + w;
    const float* p = (row < B_ROWS) ? src + (size_t)row * D
                                    : tgt + (size_t)(row - B_ROWS) * D;
    float4 v0 = *(const float4*)(p + l * 4);
    float4 v1 = *(const float4*)(p + 128 + l * 4);

    __nv_bfloat162* ob = (__nv_bfloat162*)(g_bf16 + (size_t)row * D);
    ob[l * 2 + 0]      = __floats2bfloat162_rn(v0.x, v0.y);
    ob[l * 2 + 1]      = __floats2bfloat162_rn(v0.z, v0.w);
    ob[64 + l * 2 + 0] = __floats2bfloat162_rn(v1.x, v1.y);
    ob[64 + l * 2 + 1] = __floats2bfloat162_rn(v1.z, v1.w);

    float sq = v0.x * v0.x + v0.y * v0.y + v0.z * v0.z + v0.w * v0.w
             + v1.x * v1.x + v1.y * v1.y + v1.z * v1.z + v1.w * v1.w;
    #pragma unroll
    for (int s = 16; s; s >>= 1) sq += __shfl_xor_sync(0xFFFFFFFFu, sq, s);
    if (l == 0) { g_sq[row] = sq; swsq[w] = sq; }

    atomicAdd(&scol[l * 4 + 0], (double)v0.x);
    atomicAdd(&scol[l * 4 + 1], (double)v0.y);
    atomicAdd(&scol[l * 4 + 2], (double)v0.z);
    atomicAdd(&scol[l * 4 + 3], (double)v0.w);
    atomicAdd(&scol[128 + l * 4 + 0], (double)v1.x);
    atomicAdd(&scol[128 + l * 4 + 1], (double)v1.y);
    atomicAdd(&scol[128 + l * 4 + 2], (double)v1.z);
    atomicAdd(&scol[128 + l * 4 + 3], (double)v1.w);
    __syncthreads();

    atomicAdd(&g_colsum[t], scol[t]);
    if (t == 0) {
        double s = 0;
        #pragma unroll
        for (int i = 0; i < 8; i++) s += (double)swsq[i];
        atomicAdd(&g_sumsq, s);
    }
}

// ---------------------------------------------------------------------------
// k_bw: bandwidth from sum(L2) = 2n*sumsq - 2*|colsum|^2
// ---------------------------------------------------------------------------
__global__ void k_bw() {
    __shared__ double red[256];
    int t = threadIdx.x;
    double c = g_colsum[t];
    red[t] = c * c;
    __syncthreads();
    #pragma unroll
    for (int s = 128; s > 0; s >>= 1) {
        if (t < s) red[t] += red[t + s];
        __syncthreads();
    }
    if (t == 0) {
        double n = (double)NROWS;
        double sumL2 = 2.0 * n * g_sumsq - 2.0 * red[0];
        double bw = sumL2 / (n * n - n) * 0.25;   // / 2^(KERNEL_NUM//2)
        g_c2 = (float)(-1.0 / (16.0 * bw * 0.6931471805599453094));
    }
}

// ---------------------------------------------------------------------------
// k_mma: one upper-tri 128x128 tile pair per CTA.
//   bf16 mma.sync (HMMA tensor path), fp32 accum in registers,
//   K streamed in 4 x 64 with cp.async double buffering,
//   fused exp epilogue + block reduce, one atomicAdd per CTA.
// 8 warps, warp tile = 32 (M) x 64 (N).
// ---------------------------------------------------------------------------
extern __shared__ char dynsmem[];

__global__ void __launch_bounds__(256, 2) k_mma() {
    __shared__ float  s_c2sqi[TILE];
    __shared__ float  s_c2sqj[TILE];
    __shared__ double sred[256];

    const int t = threadIdx.x;
    const int w = t >> 5, l = t & 31;

    // decode upper-tri pair (I <= J)
    int I = 0, rem = blockIdx.x;
    while (rem >= NT - I) { rem -= NT - I; I++; }
    const int J = I + rem;

    const float c2 = g_c2;
    if (t < TILE) {
        s_c2sqi[t] = c2 * g_sq[I * TILE + t];
        s_c2sqj[t] = c2 * g_sq[J * TILE + t];
    }

    const __nv_bfloat16* Abase = g_bf16 + (size_t)I * TILE * D;
    const __nv_bfloat16* Bbase = g_bf16 + (size_t)J * TILE * D;
    const uint32_t sdyn = smem_u32(dynsmem);

    // ---- cp.async staging helpers: 2048 x 16B chunks per K-chunk ----
    // idx -> op (A/B), row (0..127), ch (16B chunk 0..7 in a 128B row)
    // swizzled dst offset = row*128 + ((ch ^ (row&7)) * 16)
    auto stage = [&](int kc, int buf) {
        #pragma unroll
        for (int i = 0; i < 8; i++) {
            int idx = t + i * 256;
            int op  = idx >> 10;
            int li  = idx & 1023;
            int row = li >> 3;
            int ch  = li & 7;
            const __nv_bfloat16* gp =
                (op ? Bbase : Abase) + (size_t)row * D + kc * BK + ch * 8;
            uint32_t dst = sdyn + (uint32_t)buf * BUFB + (uint32_t)op * ABYTES
                         + (uint32_t)(row * 128 + (((ch ^ (row & 7)) << 4)));
            cpasync16(dst, gp);
        }
        CP_COMMIT();
    };

    // ---- per-lane ldmatrix base offsets ----
    const int wm = (w >> 1) * 32;    // warp M offset (0,32,64,96)
    const int wn = (w & 1) * 64;     // warp N offset (0,64)
    const uint32_t xr  = (uint32_t)((l & 7) << 4);         // swizzle XOR
    const uint32_t arow = (uint32_t)(wm + (l & 15));       // A lane row
    const uint32_t khA  = (uint32_t)(l >> 4);              // 0/1
    const uint32_t brow = (uint32_t)(wn + (l & 7) + ((l & 16) ? 8 : 0));
    const uint32_t khB  = (uint32_t)((l >> 3) & 1);

    float acc[2][8][4];
    #pragma unroll
    for (int mi = 0; mi < 2; mi++)
        #pragma unroll
        for (int ni = 0; ni < 8; ni++)
            #pragma unroll
            for (int c = 0; c < 4; c++) acc[mi][ni][c] = 0.f;

    stage(0, 0);

    #pragma unroll 1
    for (int kc = 0; kc < NKC; kc++) {
        if (kc + 1 < NKC) stage(kc + 1, (kc + 1) & 1);
        if (kc + 1 < NKC) { CP_WAIT(1); } else { CP_WAIT(0); }
        __syncthreads();

        const uint32_t bo = (uint32_t)(kc & 1) * BUFB;
        const uint32_t aB = sdyn + bo + arow * 128u;
        const uint32_t bB = sdyn + bo + ABYTES + brow * 128u;

        #pragma unroll
        for (int kk = 0; kk < 4; kk++) {
            uint32_t ka = ((uint32_t)(kk * 32) + khA * 16u) ^ xr;
            uint32_t kb = ((uint32_t)(kk * 32) + khB * 16u) ^ xr;
            uint32_t af[2][4], bf[4][4];
            LDSM4(af[0], aB + ka);
            LDSM4(af[1], aB + 2048u + ka);
            LDSM4(bf[0], bB + kb);
            LDSM4(bf[1], bB + 2048u + kb);
            LDSM4(bf[2], bB + 4096u + kb);
            LDSM4(bf[3], bB + 6144u + kb);
            #pragma unroll
            for (int mi = 0; mi < 2; mi++)
                #pragma unroll
                for (int nj = 0; nj < 4; nj++) {
                    MMA16816(acc[mi][nj * 2 + 0], af[mi], bf[nj][0], bf[nj][1]);
                    MMA16816(acc[mi][nj * 2 + 1], af[mi], bf[nj][2], bf[nj][3]);
                }
        }
        __syncthreads();
    }

    // ---- fused epilogue ----
    // element (mi,ni,c): m = wm + mi*16 + gr + (c>=2)*8 ; n = wn + ni*8 + gc + (c&1)
    const int gr = l >> 2;
    const int gc = (l & 3) * 2;
    const float m2c2 = -2.0f * c2;
    const bool diag = (I == J);

    float rb[2][2];
    #pragma unroll
    for (int mi = 0; mi < 2; mi++)
        #pragma unroll
        for (int rh = 0; rh < 2; rh++)
            rb[mi][rh] = s_c2sqi[wm + mi * 16 + rh * 8 + gr];
    float cv[8][2];
    #pragma unroll
    for (int ni = 0; ni < 8; ni++)
        #pragma unroll
        for (int cc = 0; cc < 2; cc++)
            cv[ni][cc] = s_c2sqj[wn + ni * 8 + gc + cc];

    float facc = 0.f;
    #pragma unroll
    for (int mi = 0; mi < 2; mi++) {
        #pragma unroll
        for (int ni = 0; ni < 8; ni++) {
            #pragma unroll
            for (int c = 0; c < 4; c++) {
                int rh = c >> 1, cc = c & 1;
                float arg = fmaf(acc[mi][ni][c], m2c2, rb[mi][rh] + cv[ni][cc]);
                float u = ex2f(arg);
                float u2 = u * u, u4 = u2 * u2, u8 = u4 * u4, u16 = u8 * u8;
                float kv = ((u + u2) + (u4 + u8)) + u16;
                bool take = true;
                if (diag) {
                    int mm = wm + mi * 16 + rh * 8 + gr;
                    int nn = wn + ni * 8 + gc + cc;
                    take = nn > mm;          // strict upper triangle in diag tile
                }
                facc += take ? kv : 0.f;
            }
        }
    }

    // block reduction in double, one atomic per CTA
    const double sg = ((I < NT / 2) == (J < NT / 2)) ? 1.0 : -1.0;
    sred[t] = (double)facc * sg;
    __syncthreads();
    #pragma unroll
    for (int s = 128; s > 0; s >>= 1) {
        if (t < s) sred[t] += sred[t + s];
        __syncthreads();
    }
    if (t == 0) atomicAdd(&g_acc, sred[0]);
}

// ---------------------------------------------------------------------------
// k_fin: result = (2*sum_{i<j} + 5*n) / b^2   (diagonal K_ii = 5 exactly)
// ---------------------------------------------------------------------------
__global__ void k_fin(float* out) {
    out[0] = (float)((2.0 * g_acc + 5.0 * (double)NROWS)
                     / ((double)B_ROWS * (double)B_ROWS));
}

extern "C" void kernel_launch(void* const* d_in, const int* in_sizes, int n_in,
                              void* d_out, int out_size) {
    const float* src = (const float*)d_in[0];
    const float* tgt = (const float*)d_in[1];
    float* out = (float*)d_out;

    static const int kDynSmem = 2 * BUFB;   // 64 KB double-buffered A/B
    cudaFuncSetAttribute(k_mma, cudaFuncAttributeMaxDynamicSharedMemorySize, kDynSmem);

    k_init<<<1, 256>>>();
    k_prep<<<NROWS / 8, 256>>>(src, tgt);
    k_bw<<<1, 256>>>();
    k_mma<<<NPAIRS, 256, kDynSmem>>>();
    k_fin<<<1, 1>>>(out);
}

// round 6
// speedup vs baseline: 5.6696x; 1.2764x over previous
#include <cuda_runtime.h>
#include <cuda_bf16.h>
#include <cstdint>

// Problem constants (fixed: source/target are [4096, 256] f32)
#define B_ROWS 4096
#define NROWS  8192
#define D      256
#define TILE   128
#define NT     (NROWS / TILE)          // 64 tiles per side
#define NPAIRS (NT * (NT + 1) / 2)     // 2080 upper-tri tile pairs
#define BK     64                      // K chunk
#define NKC    (D / BK)                // 4 chunks
#define ABYTES (TILE * BK * 2)         // 16384 bytes per operand chunk
#define BUFB   (2 * ABYTES)            // 32768 bytes per double-buffer slot

// ---- device scratch (no allocations allowed) ----
__device__ __align__(16) __nv_bfloat16 g_bf16[NROWS * D];  // 4 MB converted inputs
__device__ float  g_sq[NROWS];
__device__ float  g_colsum[D];
__device__ double g_sumsq;
__device__ double g_acc;
__device__ float  g_c2;   // u = exp2(c2 * L2) = exp(-L2/(16*bw))

// ---------------------------------------------------------------------------
// PTX helpers (baseline PTX only -- compiles for compute_103)
// ---------------------------------------------------------------------------
__device__ __forceinline__ float ex2f(float x) {
    float y; asm("ex2.approx.ftz.f32 %0, %1;" : "=f"(y) : "f"(x)); return y;
}
__device__ __forceinline__ uint32_t smem_u32(const void* p) {
    uint32_t a;
    asm("{ .reg .u64 t; cvta.to.shared.u64 t, %1; cvt.u32.u64 %0, t; }"
        : "=r"(a) : "l"(p));
    return a;
}
__device__ __forceinline__ void cpasync16(uint32_t dst, const void* src) {
    asm volatile("cp.async.cg.shared.global [%0], [%1], 16;"
                 :: "r"(dst), "l"(src) : "memory");
}
#define CP_COMMIT() asm volatile("cp.async.commit_group;" ::: "memory")
#define CP_WAIT(n)  asm volatile("cp.async.wait_group %0;" :: "n"(n) : "memory")

#define LDSM4(r, addr) \
    asm volatile("ldmatrix.sync.aligned.m8n8.x4.shared.b16 {%0,%1,%2,%3}, [%4];" \
                 : "=r"((r)[0]), "=r"((r)[1]), "=r"((r)[2]), "=r"((r)[3]) \
                 : "r"(addr))

#define MMA16816(d, a, b0, b1) \
    asm volatile("mma.sync.aligned.m16n8k16.row.col.f32.bf16.bf16.f32 " \
                 "{%0,%1,%2,%3}, {%4,%5,%6,%7}, {%8,%9}, {%0,%1,%2,%3};" \
                 : "+f"((d)[0]), "+f"((d)[1]), "+f"((d)[2]), "+f"((d)[3]) \
                 : "r"((a)[0]), "r"((a)[1]), "r"((a)[2]), "r"((a)[3]), \
                   "r"(b0), "r"(b1))

// ---------------------------------------------------------------------------
// k_init: zero accumulators each replay
// ---------------------------------------------------------------------------
__global__ void k_init() {
    int t = threadIdx.x;
    if (t < D) g_colsum[t] = 0.f;
    if (t == 0) { g_sumsq = 0.0; g_acc = 0.0; }
}

// ---------------------------------------------------------------------------
// k_prep: f32 -> bf16 conversion + row sq-norms + column sums (atomic-light).
// 256 blocks x 256 threads; thread t owns column t; block handles 32 rows.
// ---------------------------------------------------------------------------
__global__ void k_prep(const float* __restrict__ src, const float* __restrict__ tgt) {
    __shared__ float swsq[32][8];
    const int t = threadIdx.x, w = t >> 5, l = t & 31;
    const int r0 = blockIdx.x * 32;

    float colsum = 0.f;
    #pragma unroll 4
    for (int r = 0; r < 32; r++) {
        int row = r0 + r;
        const float* p = (row < B_ROWS) ? src + (size_t)row * D
                                        : tgt + (size_t)(row - B_ROWS) * D;
        float v = p[t];
        g_bf16[(size_t)row * D + t] = __float2bfloat16(v);
        colsum += v;
        float s = v * v;
        #pragma unroll
        for (int k = 16; k; k >>= 1) s += __shfl_xor_sync(0xFFFFFFFFu, s, k);
        if (l == 0) swsq[r][w] = s;
    }
    __syncthreads();
    atomicAdd(&g_colsum[t], colsum);
    if (t < 32) {
        float sq = 0.f;
        #pragma unroll
        for (int i = 0; i < 8; i++) sq += swsq[t][i];
        g_sq[r0 + t] = sq;
        float bs = sq;
        #pragma unroll
        for (int k = 16; k; k >>= 1) bs += __shfl_xor_sync(0xFFFFFFFFu, bs, k);
        if (t == 0) atomicAdd(&g_sumsq, (double)bs);
    }
}

// ---------------------------------------------------------------------------
// k_bw: bandwidth from sum(L2) = 2n*sumsq - 2*|colsum|^2
// ---------------------------------------------------------------------------
__global__ void k_bw() {
    __shared__ double red[256];
    int t = threadIdx.x;
    double c = (double)g_colsum[t];
    red[t] = c * c;
    __syncthreads();
    #pragma unroll
    for (int s = 128; s > 0; s >>= 1) {
        if (t < s) red[t] += red[t + s];
        __syncthreads();
    }
    if (t == 0) {
        double n = (double)NROWS;
        double sumL2 = 2.0 * n * g_sumsq - 2.0 * red[0];
        double bw = sumL2 / (n * n - n) * 0.25;   // / 2^(KERNEL_NUM//2)
        g_c2 = (float)(-1.0 / (16.0 * bw * 0.6931471805599453094));
    }
}

// ---------------------------------------------------------------------------
// k_mma: one upper-tri 128x128 tile pair per CTA.  (R3-proven version)
//   bf16 mma.sync, fp32 accum, K streamed in 4 x 64 with cp.async double
//   buffering, fused exp epilogue + block reduce, one atomicAdd per CTA.
// 8 warps, warp tile = 32 (M) x 64 (N).
// ---------------------------------------------------------------------------
extern __shared__ char dynsmem[];

__global__ void __launch_bounds__(256, 2) k_mma() {
    __shared__ float  s_c2sqi[TILE];
    __shared__ float  s_c2sqj[TILE];
    __shared__ double sred[256];

    const int t = threadIdx.x;
    const int w = t >> 5, l = t & 31;

    // decode upper-tri pair (I <= J)
    int I = 0, rem = blockIdx.x;
    while (rem >= NT - I) { rem -= NT - I; I++; }
    const int J = I + rem;

    const float c2 = g_c2;
    if (t < TILE) {
        s_c2sqi[t] = c2 * g_sq[I * TILE + t];
        s_c2sqj[t] = c2 * g_sq[J * TILE + t];
    }

    const __nv_bfloat16* Abase = g_bf16 + (size_t)I * TILE * D;
    const __nv_bfloat16* Bbase = g_bf16 + (size_t)J * TILE * D;
    const uint32_t sdyn = smem_u32(dynsmem);

    // ---- cp.async staging: 2048 x 16B chunks per K-chunk ----
    // idx -> op (A/B), row (0..127), ch (16B chunk 0..7 in a 128B row)
    // swizzled dst offset = row*128 + ((ch ^ (row&7)) * 16)
    auto stage = [&](int kc, int buf) {
        #pragma unroll
        for (int i = 0; i < 8; i++) {
            int idx = t + i * 256;
            int op  = idx >> 10;
            int li  = idx & 1023;
            int row = li >> 3;
            int ch  = li & 7;
            const __nv_bfloat16* gp =
                (op ? Bbase : Abase) + (size_t)row * D + kc * BK + ch * 8;
            uint32_t dst = sdyn + (uint32_t)buf * BUFB + (uint32_t)op * ABYTES
                         + (uint32_t)(row * 128 + (((ch ^ (row & 7)) << 4)));
            cpasync16(dst, gp);
        }
        CP_COMMIT();
    };

    // ---- per-lane ldmatrix base offsets ----
    const int wm = (w >> 1) * 32;    // warp M offset (0,32,64,96)
    const int wn = (w & 1) * 64;     // warp N offset (0,64)
    const uint32_t xr   = (uint32_t)((l & 7) << 4);        // swizzle XOR
    const uint32_t arow = (uint32_t)(wm + (l & 15));
    const uint32_t khA  = (uint32_t)(l >> 4);
    const uint32_t brow = (uint32_t)(wn + (l & 7) + ((l & 16) ? 8 : 0));
    const uint32_t khB  = (uint32_t)((l >> 3) & 1);

    float acc[2][8][4];
    #pragma unroll
    for (int mi = 0; mi < 2; mi++)
        #pragma unroll
        for (int ni = 0; ni < 8; ni++)
            #pragma unroll
            for (int c = 0; c < 4; c++) acc[mi][ni][c] = 0.f;

    stage(0, 0);

    #pragma unroll 1
    for (int kc = 0; kc < NKC; kc++) {
        if (kc + 1 < NKC) stage(kc + 1, (kc + 1) & 1);
        if (kc + 1 < NKC) { CP_WAIT(1); } else { CP_WAIT(0); }
        __syncthreads();

        const uint32_t bo = (uint32_t)(kc & 1) * BUFB;
        const uint32_t aB = sdyn + bo + arow * 128u;
        const uint32_t bB = sdyn + bo + ABYTES + brow * 128u;

        #pragma unroll
        for (int kk = 0; kk < 4; kk++) {
            uint32_t ka = ((uint32_t)(kk * 32) + khA * 16u) ^ xr;
            uint32_t kb = ((uint32_t)(kk * 32) + khB * 16u) ^ xr;
            uint32_t af[2][4], bf[4][4];
            LDSM4(af[0], aB + ka);
            LDSM4(af[1], aB + 2048u + ka);
            LDSM4(bf[0], bB + kb);
            LDSM4(bf[1], bB + 2048u + kb);
            LDSM4(bf[2], bB + 4096u + kb);
            LDSM4(bf[3], bB + 6144u + kb);
            #pragma unroll
            for (int mi = 0; mi < 2; mi++)
                #pragma unroll
                for (int nj = 0; nj < 4; nj++) {
                    MMA16816(acc[mi][nj * 2 + 0], af[mi], bf[nj][0], bf[nj][1]);
                    MMA16816(acc[mi][nj * 2 + 1], af[mi], bf[nj][2], bf[nj][3]);
                }
        }
        __syncthreads();
    }

    // ---- fused epilogue ----
    // element (mi,ni,c): m = wm + mi*16 + gr + (c>=2)*8 ; n = wn + ni*8 + gc + (c&1)
    const int gr = l >> 2;
    const int gc = (l & 3) * 2;
    const float m2c2 = -2.0f * c2;
    const bool diag = (I == J);

    float rb[2][2];
    #pragma unroll
    for (int mi = 0; mi < 2; mi++)
        #pragma unroll
        for (int rh = 0; rh < 2; rh++)
            rb[mi][rh] = s_c2sqi[wm + mi * 16 + rh * 8 + gr];
    float cv[8][2];
    #pragma unroll
    for (int ni = 0; ni < 8; ni++)
        #pragma unroll
        for (int cc = 0; cc < 2; cc++)
            cv[ni][cc] = s_c2sqj[wn + ni * 8 + gc + cc];

    float facc = 0.f;
    #pragma unroll
    for (int mi = 0; mi < 2; mi++) {
        #pragma unroll
        for (int ni = 0; ni < 8; ni++) {
            #pragma unroll
            for (int c = 0; c < 4; c++) {
                int rh = c >> 1, cc = c & 1;
                float arg = fmaf(acc[mi][ni][c], m2c2, rb[mi][rh] + cv[ni][cc]);
                float u = ex2f(arg);
                float u2 = u * u, u4 = u2 * u2, u8 = u4 * u4, u16 = u8 * u8;
                float kv = ((u + u2) + (u4 + u8)) + u16;
                bool take = true;
                if (diag) {
                    int mm = wm + mi * 16 + rh * 8 + gr;
                    int nn = wn + ni * 8 + gc + cc;
                    take = nn > mm;          // strict upper triangle in diag tile
                }
                facc += take ? kv : 0.f;
            }
        }
    }

    // block reduction in double, one atomic per CTA
    const double sg = ((I < NT / 2) == (J < NT / 2)) ? 1.0 : -1.0;
    sred[t] = (double)facc * sg;
    __syncthreads();
    #pragma unroll
    for (int s = 128; s > 0; s >>= 1) {
        if (t < s) sred[t] += sred[t + s];
        __syncthreads();
    }
    if (t == 0) atomicAdd(&g_acc, sred[0]);
}

// ---------------------------------------------------------------------------
// k_fin: result = (2*sum_{i<j} + 5*n) / b^2   (diagonal K_ii = 5 exactly)
// ---------------------------------------------------------------------------
__global__ void k_fin(float* out) {
    out[0] = (float)((2.0 * g_acc + 5.0 * (double)NROWS)
                     / ((double)B_ROWS * (double)B_ROWS));
}

extern "C" void kernel_launch(void* const* d_in, const int* in_sizes, int n_in,
                              void* d_out, int out_size) {
    const float* src = (const float*)d_in[0];
    const float* tgt = (const float*)d_in[1];
    float* out = (float*)d_out;

    static const int kDynSmem = 2 * BUFB;   // 64 KB double-buffered A/B
    cudaFuncSetAttribute(k_mma, cudaFuncAttributeMaxDynamicSharedMemorySize, kDynSmem);

    k_init<<<1, 256>>>();
    k_prep<<<NROWS / 32, 256>>>(src, tgt);
    k_bw<<<1, 256>>>();
    k_mma<<<NPAIRS, 256, kDynSmem>>>();
    k_fin<<<1, 1>>>(out);
}

// round 7
// speedup vs baseline: 5.6746x; 1.0009x over previous
#include <cuda_runtime.h>
#include <cuda_bf16.h>
#include <cstdint>

// Problem constants (fixed: source/target are [4096, 256] f32)
#define B_ROWS 4096
#define NROWS  8192
#define D      256
#define TILE   128
#define NT     (NROWS / TILE)          // 64 tiles per side
#define NPAIRS (NT * (NT + 1) / 2)     // 2080 upper-tri tile pairs
#define BK     64                      // K chunk
#define NKC    (D / BK)                // 4 chunks
#define ABYTES (TILE * BK * 2)         // 16384 bytes per operand chunk
#define BUFB   (2 * ABYTES)            // 32768 bytes per double-buffer slot

// ---- device scratch (no allocations allowed; zero-initialized at load) ----
__device__ __align__(16) __nv_bfloat16 g_bf16[NROWS * D];  // 4 MB converted inputs
__device__ float    g_sq[NROWS];
__device__ float    g_colsum[D];
__device__ double   g_sumsq;
__device__ double   g_acc;
__device__ float    g_c2;     // u = exp2(c2 * L2) = exp(-L2/(16*bw))
__device__ unsigned g_tick;   // k_prep completion ticket

// ---------------------------------------------------------------------------
// PTX helpers (baseline PTX only -- compiles for compute_103)
// ---------------------------------------------------------------------------
__device__ __forceinline__ float ex2f(float x) {
    float y; asm("ex2.approx.ftz.f32 %0, %1;" : "=f"(y) : "f"(x)); return y;
}
__device__ __forceinline__ uint32_t smem_u32(const void* p) {
    uint32_t a;
    asm("{ .reg .u64 t; cvta.to.shared.u64 t, %1; cvt.u32.u64 %0, t; }"
        : "=r"(a) : "l"(p));
    return a;
}
__device__ __forceinline__ void cpasync16(uint32_t dst, const void* src) {
    asm volatile("cp.async.cg.shared.global [%0], [%1], 16;"
                 :: "r"(dst), "l"(src) : "memory");
}
#define CP_COMMIT() asm volatile("cp.async.commit_group;" ::: "memory")
#define CP_WAIT(n)  asm volatile("cp.async.wait_group %0;" :: "n"(n) : "memory")

#define LDSM4(r, addr) \
    asm volatile("ldmatrix.sync.aligned.m8n8.x4.shared.b16 {%0,%1,%2,%3}, [%4];" \
                 : "=r"((r)[0]), "=r"((r)[1]), "=r"((r)[2]), "=r"((r)[3]) \
                 : "r"(addr))

#define MMA16816(d, a, b0, b1) \
    asm volatile("mma.sync.aligned.m16n8k16.row.col.f32.bf16.bf16.f32 " \
                 "{%0,%1,%2,%3}, {%4,%5,%6,%7}, {%8,%9}, {%0,%1,%2,%3};" \
                 : "+f"((d)[0]), "+f"((d)[1]), "+f"((d)[2]), "+f"((d)[3]) \
                 : "r"((a)[0]), "r"((a)[1]), "r"((a)[2]), "r"((a)[3]), \
                   "r"(b0), "r"(b1))

// L2-coherent loads (read values produced by other blocks' atomics)
__device__ __forceinline__ float ldcg_f(const float* p) {
    float v; asm volatile("ld.global.cg.f32 %0, [%1];" : "=f"(v) : "l"(p)); return v;
}
__device__ __forceinline__ double ldcg_d(const double* p) {
    double v; asm volatile("ld.global.cg.f64 %0, [%1];" : "=d"(v) : "l"(p)); return v;
}

// ---- packed f32x2 (PTX ISA 8.6, base sm_100 family -- register-only ops) ----
__device__ __forceinline__ uint64_t pk2(float lo, float hi) {
    uint64_t r; asm("mov.b64 %0, {%1, %2};" : "=l"(r) : "f"(lo), "f"(hi)); return r;
}
__device__ __forceinline__ void upk2(float& lo, float& hi, uint64_t v) {
    asm("mov.b64 {%0, %1}, %2;" : "=f"(lo), "=f"(hi) : "l"(v));
}
__device__ __forceinline__ uint64_t fma2p(uint64_t a, uint64_t b, uint64_t c) {
    uint64_t d; asm("fma.rn.f32x2 %0, %1, %2, %3;" : "=l"(d) : "l"(a), "l"(b), "l"(c)); return d;
}
__device__ __forceinline__ uint64_t mul2p(uint64_t a, uint64_t b) {
    uint64_t d; asm("mul.rn.f32x2 %0, %1, %2;" : "=l"(d) : "l"(a), "l"(b)); return d;
}
__device__ __forceinline__ uint64_t add2p(uint64_t a, uint64_t b) {
    uint64_t d; asm("add.rn.f32x2 %0, %1, %2;" : "=l"(d) : "l"(a), "l"(b)); return d;
}

// ---------------------------------------------------------------------------
// k_prep: f32 -> bf16 conversion + row sq-norms + column sums; the LAST block
// (atomic ticket) computes the bandwidth constant and resets the accumulators
// for the next graph replay (self-cleaning: no k_init / k_bw launches).
// 256 blocks x 256 threads; thread t owns column t; block handles 32 rows.
// ---------------------------------------------------------------------------
__global__ void k_prep(const float* __restrict__ src, const float* __restrict__ tgt) {
    __shared__ float    swsq[32][8];
    __shared__ unsigned s_last;
    __shared__ double   dred[256];
    const int t = threadIdx.x, w = t >> 5, l = t & 31;
    const int r0 = blockIdx.x * 32;

    float colsum = 0.f;
    #pragma unroll 4
    for (int r = 0; r < 32; r++) {
        int row = r0 + r;
        const float* p = (row < B_ROWS) ? src + (size_t)row * D
                                        : tgt + (size_t)(row - B_ROWS) * D;
        float v = p[t];
        g_bf16[(size_t)row * D + t] = __float2bfloat16(v);
        colsum += v;
        float s = v * v;
        #pragma unroll
        for (int k = 16; k; k >>= 1) s += __shfl_xor_sync(0xFFFFFFFFu, s, k);
        if (l == 0) swsq[r][w] = s;
    }
    __syncthreads();
    atomicAdd(&g_colsum[t], colsum);
    if (t < 32) {
        float sq = 0.f;
        #pragma unroll
        for (int i = 0; i < 8; i++) sq += swsq[t][i];
        g_sq[r0 + t] = sq;
        float bs = sq;
        #pragma unroll
        for (int k = 16; k; k >>= 1) bs += __shfl_xor_sync(0xFFFFFFFFu, bs, k);
        if (t == 0) atomicAdd(&g_sumsq, (double)bs);
    }

    // ---- ticket: last block computes bandwidth + resets state ----
    __threadfence();
    __syncthreads();
    if (t == 0) s_last = (atomicAdd(&g_tick, 1u) == (unsigned)(gridDim.x - 1));
    __syncthreads();
    if (s_last) {
        double c = (double)ldcg_f(&g_colsum[t]);
        dred[t] = c * c;
        __syncthreads();
        #pragma unroll
        for (int s = 128; s > 0; s >>= 1) {
            if (t < s) dred[t] += dred[t + s];
            __syncthreads();
        }
        if (t == 0) {
            double n = (double)NROWS;
            double sumsq = ldcg_d(&g_sumsq);
            double sumL2 = 2.0 * n * sumsq - 2.0 * dred[0];
            double bw = sumL2 / (n * n - n) * 0.25;   // / 2^(KERNEL_NUM//2)
            g_c2 = (float)(-1.0 / (16.0 * bw * 0.6931471805599453094));
            g_sumsq = 0.0;
            g_tick  = 0u;
        }
        g_colsum[t] = 0.f;      // clean for next replay
    }
}

// ---------------------------------------------------------------------------
// k_mma: one upper-tri 128x128 tile pair per CTA.  (R3/R6-proven mainloop)
//   bf16 mma.sync, fp32 accum, K streamed in 4 x 64 with cp.async double
//   buffering, packed-f32x2 exp epilogue, shuffle reduce, one atomic per CTA.
// 8 warps, warp tile = 32 (M) x 64 (N).
// ---------------------------------------------------------------------------
extern __shared__ char dynsmem[];

__global__ void __launch_bounds__(256, 2) k_mma() {
    __shared__ float  s_c2sqi[TILE];
    __shared__ float  s_c2sqj[TILE];
    __shared__ double sp8[8];

    const int t = threadIdx.x;
    const int w = t >> 5, l = t & 31;

    // decode upper-tri pair (I <= J)
    int I = 0, rem = blockIdx.x;
    while (rem >= NT - I) { rem -= NT - I; I++; }
    const int J = I + rem;

    const float c2 = g_c2;
    if (t < TILE) {
        s_c2sqi[t] = c2 * g_sq[I * TILE + t];
        s_c2sqj[t] = c2 * g_sq[J * TILE + t];
    }

    const __nv_bfloat16* Abase = g_bf16 + (size_t)I * TILE * D;
    const __nv_bfloat16* Bbase = g_bf16 + (size_t)J * TILE * D;
    const uint32_t sdyn = smem_u32(dynsmem);

    // ---- cp.async staging: 2048 x 16B chunks per K-chunk ----
    auto stage = [&](int kc, int buf) {
        #pragma unroll
        for (int i = 0; i < 8; i++) {
            int idx = t + i * 256;
            int op  = idx >> 10;
            int li  = idx & 1023;
            int row = li >> 3;
            int ch  = li & 7;
            const __nv_bfloat16* gp =
                (op ? Bbase : Abase) + (size_t)row * D + kc * BK + ch * 8;
            uint32_t dst = sdyn + (uint32_t)buf * BUFB + (uint32_t)op * ABYTES
                         + (uint32_t)(row * 128 + (((ch ^ (row & 7)) << 4)));
            cpasync16(dst, gp);
        }
        CP_COMMIT();
    };

    // ---- per-lane ldmatrix base offsets ----
    const int wm = (w >> 1) * 32;    // warp M offset (0,32,64,96)
    const int wn = (w & 1) * 64;     // warp N offset (0,64)
    const uint32_t xr   = (uint32_t)((l & 7) << 4);        // swizzle XOR
    const uint32_t arow = (uint32_t)(wm + (l & 15));
    const uint32_t khA  = (uint32_t)(l >> 4);
    const uint32_t brow = (uint32_t)(wn + (l & 7) + ((l & 16) ? 8 : 0));
    const uint32_t khB  = (uint32_t)((l >> 3) & 1);

    float acc[2][8][4];
    #pragma unroll
    for (int mi = 0; mi < 2; mi++)
        #pragma unroll
        for (int ni = 0; ni < 8; ni++)
            #pragma unroll
            for (int c = 0; c < 4; c++) acc[mi][ni][c] = 0.f;

    stage(0, 0);

    #pragma unroll 1
    for (int kc = 0; kc < NKC; kc++) {
        if (kc + 1 < NKC) stage(kc + 1, (kc + 1) & 1);
        if (kc + 1 < NKC) { CP_WAIT(1); } else { CP_WAIT(0); }
        __syncthreads();

        const uint32_t bo = (uint32_t)(kc & 1) * BUFB;
        const uint32_t aB = sdyn + bo + arow * 128u;
        const uint32_t bB = sdyn + bo + ABYTES + brow * 128u;

        #pragma unroll
        for (int kk = 0; kk < 4; kk++) {
            uint32_t ka = ((uint32_t)(kk * 32) + khA * 16u) ^ xr;
            uint32_t kb = ((uint32_t)(kk * 32) + khB * 16u) ^ xr;
            uint32_t af[2][4], bf[4][4];
            LDSM4(af[0], aB + ka);
            LDSM4(af[1], aB + 2048u + ka);
            LDSM4(bf[0], bB + kb);
            LDSM4(bf[1], bB + 2048u + kb);
            LDSM4(bf[2], bB + 4096u + kb);
            LDSM4(bf[3], bB + 6144u + kb);
            #pragma unroll
            for (int mi = 0; mi < 2; mi++)
                #pragma unroll
                for (int nj = 0; nj < 4; nj++) {
                    MMA16816(acc[mi][nj * 2 + 0], af[mi], bf[nj][0], bf[nj][1]);
                    MMA16816(acc[mi][nj * 2 + 1], af[mi], bf[nj][2], bf[nj][3]);
                }
        }
        __syncthreads();
    }

    // ---- fused epilogue ----
    // element (mi,ni,c): m = wm + mi*16 + gr + (c>=2)*8 ; n = wn + ni*8 + gc + (c&1)
    const int gr = l >> 2;
    const int gc = (l & 3) * 2;
    const float m2c2 = -2.0f * c2;
    const bool diag = (I == J);

    float facc = 0.f;
    if (!diag) {
        // packed f32x2 path: scalar smem loads, register-only packing
        const uint64_t m2c2p = pk2(m2c2, m2c2);
        uint64_t rbp[2][2];
        #pragma unroll
        for (int mi = 0; mi < 2; mi++)
            #pragma unroll
            for (int rh = 0; rh < 2; rh++) {
                float rv = s_c2sqi[wm + mi * 16 + rh * 8 + gr];
                rbp[mi][rh] = pk2(rv, rv);
            }
        uint64_t cvp[8];
        #pragma unroll
        for (int ni = 0; ni < 8; ni++) {
            float c0 = s_c2sqj[wn + ni * 8 + gc];
            float c1 = s_c2sqj[wn + ni * 8 + gc + 1];
            cvp[ni] = pk2(c0, c1);
        }
        uint64_t faccp = pk2(0.f, 0.f);
        #pragma unroll
        for (int mi = 0; mi < 2; mi++)
            #pragma unroll
            for (int ni = 0; ni < 8; ni++)
                #pragma unroll
                for (int rh = 0; rh < 2; rh++) {
                    uint64_t accp = pk2(acc[mi][ni][rh * 2], acc[mi][ni][rh * 2 + 1]);
                    uint64_t argp = fma2p(accp, m2c2p, add2p(rbp[mi][rh], cvp[ni]));
                    float a0, a1; upk2(a0, a1, argp);
                    uint64_t u  = pk2(ex2f(a0), ex2f(a1));
                    uint64_t u2 = mul2p(u, u), u4 = mul2p(u2, u2);
                    uint64_t u8 = mul2p(u4, u4), u16 = mul2p(u8, u8);
                    uint64_t s  = add2p(add2p(u, u2), add2p(u4, u8));
                    faccp = add2p(faccp, add2p(s, u16));
                }
        float f0, f1; upk2(f0, f1, faccp);
        facc = f0 + f1;
    } else {
        float rb[2][2];
        #pragma unroll
        for (int mi = 0; mi < 2; mi++)
            #pragma unroll
            for (int rh = 0; rh < 2; rh++)
                rb[mi][rh] = s_c2sqi[wm + mi * 16 + rh * 8 + gr];
        #pragma unroll
        for (int mi = 0; mi < 2; mi++)
            #pragma unroll
            for (int ni = 0; ni < 8; ni++)
                #pragma unroll
                for (int c = 0; c < 4; c++) {
                    int rh = c >> 1, cc = c & 1;
                    int mm = wm + mi * 16 + rh * 8 + gr;
                    int nn = wn + ni * 8 + gc + cc;
                    float arg = fmaf(acc[mi][ni][c], m2c2,
                                     rb[mi][rh] + s_c2sqj[nn]);
                    float u = ex2f(arg);
                    float u2 = u * u, u4 = u2 * u2, u8 = u4 * u4, u16 = u8 * u8;
                    float kv = ((u + u2) + (u4 + u8)) + u16;
                    facc += (nn > mm) ? kv : 0.f;   // strict upper triangle
                }
    }

    // block reduction: warp shuffle in double, 8 partials, one atomic
    const double sg = ((I < NT / 2) == (J < NT / 2)) ? 1.0 : -1.0;
    double dv = (double)facc * sg;
    #pragma unroll
    for (int k = 16; k; k >>= 1) dv += __shfl_xor_sync(0xFFFFFFFFu, dv, k);
    if (l == 0) sp8[w] = dv;
    __syncthreads();
    if (t == 0) {
        double s = 0.0;
        #pragma unroll
        for (int i = 0; i < 8; i++) s += sp8[i];
        atomicAdd(&g_acc, s);
    }
}

// ---------------------------------------------------------------------------
// k_fin: result = (2*sum_{i<j} + 5*n) / b^2 (diagonal K_ii = 5 exactly);
// resets g_acc for the next graph replay.
// ---------------------------------------------------------------------------
__global__ void k_fin(float* out) {
    out[0] = (float)((2.0 * g_acc + 5.0 * (double)NROWS)
                     / ((double)B_ROWS * (double)B_ROWS));
    g_acc = 0.0;
}

extern "C" void kernel_launch(void* const* d_in, const int* in_sizes, int n_in,
                              void* d_out, int out_size) {
    const float* src = (const float*)d_in[0];
    const float* tgt = (const float*)d_in[1];
    float* out = (float*)d_out;

    static const int kDynSmem = 2 * BUFB;   // 64 KB double-buffered A/B
    cudaFuncSetAttribute(k_mma, cudaFuncAttributeMaxDynamicSharedMemorySize, kDynSmem);

    k_prep<<<NROWS / 32, 256>>>(src, tgt);
    k_mma<<<NPAIRS, 256, kDynSmem>>>();
    k_fin<<<1, 1>>>(out);
}